// round 9
// baseline (speedup 1.0000x reference)
#include <cuda_runtime.h>

// SFAM_43490838839386: f = clip(tanh(x)/||tanh(x)||_2 + 0.01*noise, -1.5, 1.5)
//                      out = tanh(einsum('bi,bij->bj', f, P))
// B=4096, D=256, S=256, fp32. HBM-bound: P = 1.07 GB read once.
// R6 = R5 resubmit (infra failure): single-wave layout. 4 samples per CTA,
// 1024 CTAs (= one wave at occ 7). Each thread owns one float4 output
// column-group across the full D loop -> in-register accumulation, no
// cross-thread reduce, no second barrier. cp.async prefetch (PF=4) hides
// the phase-1 head.

#define Dk 256
#define Sk 256
#define SPC 4          // samples per CTA
#define NOISE_STD 0.01f
#define EPSN 1e-12f
#define PF 4           // prefetched i-iterations per thread

__global__ __launch_bounds__(256, 7)
void sfam_kernel(const float* __restrict__ raw,
                 const float* __restrict__ proj,
                 const float* __restrict__ noise,
                 float* __restrict__ out)
{
    __shared__ float  f_sh[SPC][Dk];
    __shared__ float  warp_sums[8];
    __shared__ float4 pf_buf[PF][256];

    const int tid  = threadIdx.x;
    const int sloc = tid >> 6;          // sample within CTA (0..3)
    const int t64  = tid & 63;          // lane within sample-group
    const int b    = blockIdx.x * SPC + sloc;

    const float* pbase = proj + (size_t)b * Dk * Sk + (size_t)t64 * 4;

    // Critical-path loads for phase 1 (4 d-values per thread, coalesced).
    float rv[4], nv[4];
    #pragma unroll
    for (int k = 0; k < 4; k++) {
        const int d = t64 + 64 * k;
        rv[k] = raw  [(size_t)b * Dk + d];
        nv[k] = noise[(size_t)b * Dk + d];
    }

    // Fire-and-forget prefetch of first PF rows of this thread's column group.
    {
        unsigned sbase = (unsigned)__cvta_generic_to_shared(&pf_buf[0][tid]);
        #pragma unroll
        for (int k = 0; k < PF; k++) {
            const float* g = pbase + (size_t)k * Sk;
            asm volatile("cp.async.cg.shared.global [%0], [%1], 16;\n"
                         :: "r"(sbase + k * 256 * 16), "l"(g));
        }
        asm volatile("cp.async.commit_group;\n");
    }

    // ---------------- Phase 1: f for this CTA's 4 samples ----------------
    float tv[4];
    float sq = 0.f;
    #pragma unroll
    for (int k = 0; k < 4; k++) {
        tv[k] = tanhf(rv[k]);
        sq = fmaf(tv[k], tv[k], sq);
    }
    #pragma unroll
    for (int o = 16; o > 0; o >>= 1)
        sq += __shfl_xor_sync(0xffffffffu, sq, o);
    const int wid = tid >> 5;
    if ((tid & 31) == 0) warp_sums[wid] = sq;
    __syncthreads();
    const float nrm = warp_sums[2 * sloc] + warp_sums[2 * sloc + 1];
    const float inv = 1.0f / fmaxf(sqrtf(nrm), EPSN);

    #pragma unroll
    for (int k = 0; k < 4; k++) {
        float fv = fmaf(tv[k], inv, NOISE_STD * nv[k]);
        fv = fminf(fmaxf(fv, -1.5f), 1.5f);
        f_sh[sloc][t64 + 64 * k] = fv;
    }
    __syncthreads();

    // ---------------- Phase 2: acc[j] = sum_i f[i] * P[b,i,j] ----------------
    const float* fs = f_sh[sloc];
    float4 acc = make_float4(0.f, 0.f, 0.f, 0.f);

    asm volatile("cp.async.wait_group 0;\n" ::: "memory");
    #pragma unroll
    for (int k = 0; k < PF; k++) {
        const float  fi = fs[k];
        const float4 p  = pf_buf[k][tid];
        acc.x = fmaf(fi, p.x, acc.x);
        acc.y = fmaf(fi, p.y, acc.y);
        acc.z = fmaf(fi, p.z, acc.z);
        acc.w = fmaf(fi, p.w, acc.w);
    }

    #pragma unroll 8
    for (int i = PF; i < Dk; i++) {
        const float  fi = fs[i];
        const float4 p  = __ldcs(reinterpret_cast<const float4*>(pbase + (size_t)i * Sk));
        acc.x = fmaf(fi, p.x, acc.x);
        acc.y = fmaf(fi, p.y, acc.y);
        acc.z = fmaf(fi, p.z, acc.z);
        acc.w = fmaf(fi, p.w, acc.w);
    }

    // Final tanh + direct coalesced streaming store (no reduction needed).
    float4 o4;
    o4.x = tanhf(acc.x);
    o4.y = tanhf(acc.y);
    o4.z = tanhf(acc.z);
    o4.w = tanhf(acc.w);
    __stcs(reinterpret_cast<float4*>(&out[(size_t)b * Sk + (size_t)t64 * 4]), o4);
}

extern "C" void kernel_launch(void* const* d_in, const int* in_sizes, int n_in,
                              void* d_out, int out_size)
{
    const float* raw   = (const float*)d_in[0];
    const float* proj  = (const float*)d_in[1];
    const float* noise = (const float*)d_in[2];
    float* out = (float*)d_out;

    const int B = in_sizes[0] / Dk;  // 4096
    sfam_kernel<<<B / SPC, 256>>>(raw, proj, noise, out);
}